// round 5
// baseline (speedup 1.0000x reference)
#include <cuda_runtime.h>
#include <cuda_bf16.h>
#include <cstdint>

#define BATCH 2048
#define DDIM  128
#define MDIM  256
#define NKEYS 32768
#define NTILE 128                  // keys per CTA tile
#define CTILES (NKEYS / NTILE)     // 256
#define EST_CONST 0.0048957583f    // float32(sqrt(pi/2)/256)
#define QSCALE 16318.72f           // 127.49 * 128

// -------- static device scratch (no allocations allowed) --------
__device__ __align__(16) signed char g_Ah[BATCH * MDIM];
__device__ __align__(16) signed char g_Al[BATCH * MDIM];
__device__ __align__(16) signed char g_Kq[(size_t)NKEYS * MDIM];
__device__ float  g_rowscale[BATCH];
__device__ float  g_part[(size_t)BATCH * CTILES * 2];
__device__ float2 g_rowstats[BATCH];

// ---------------- PTX helpers (compute_103-safe) ----------------
__device__ __forceinline__ uint32_t smem_u32(const void* p) {
    uint32_t a;
    asm("{ .reg .u64 t; cvta.to.shared.u64 t, %1; cvt.u32.u64 %0, t; }" : "=r"(a) : "l"(p));
    return a;
}
__device__ __forceinline__ void cpa16(uint32_t dst, const void* src) {
    asm volatile("cp.async.cg.shared.global [%0], [%1], 16;" :: "r"(dst), "l"(src));
}
#define CP_COMMIT() asm volatile("cp.async.commit_group;" ::: "memory")
template <int N> __device__ __forceinline__ void cp_wait() {
    asm volatile("cp.async.wait_group %0;" :: "n"(N) : "memory");
}
__device__ __forceinline__ void ldm_x4(unsigned* r, uint32_t addr) {
    asm volatile("ldmatrix.sync.aligned.m8n8.x4.shared.b16 {%0,%1,%2,%3}, [%4];"
                 : "=r"(r[0]), "=r"(r[1]), "=r"(r[2]), "=r"(r[3]) : "r"(addr));
}
__device__ __forceinline__ void imma16832(int* c, const unsigned* a, const unsigned* b) {
    asm volatile(
        "mma.sync.aligned.m16n8k32.row.col.s32.s8.s8.s32 "
        "{%0,%1,%2,%3}, {%4,%5,%6,%7}, {%8,%9}, {%0,%1,%2,%3};\n"
        : "+r"(c[0]), "+r"(c[1]), "+r"(c[2]), "+r"(c[3])
        : "r"(a[0]), "r"(a[1]), "r"(a[2]), "r"(a[3]), "r"(b[0]), "r"(b[1]));
}

// ---------------------------------------------------------------
// K0: convert keys fp32 (+/-1) -> int8 (exact)
// ---------------------------------------------------------------
__global__ void convert_keys(const float* __restrict__ keys) {
    size_t i = (size_t)blockIdx.x * blockDim.x + threadIdx.x;  // one float4 each
    float4 v = __ldg((const float4*)keys + i);
    char4 c;
    c.x = (signed char)v.x; c.y = (signed char)v.y;
    c.z = (signed char)v.z; c.w = (signed char)v.w;
    ((char4*)g_Kq)[i] = c;
}

// ---------------------------------------------------------------
// K1: PQ = query @ sketch^T (fp32) -> int8 hi/lo fixed-point split
// pq ~= s * (128*h + l),  s = rowmax/16318.72  (per batch row)
// ---------------------------------------------------------------
__global__ void project_kernel(const float* __restrict__ query,
                               const float* __restrict__ sketch) {
    __shared__ float4 qs[DDIM / 4];
    __shared__ float red[8];
    const int b = blockIdx.x;
    const int m = threadIdx.x;  // 0..255
    if (m < DDIM / 4)
        qs[m] = ((const float4*)(query + (size_t)b * DDIM))[m];
    __syncthreads();

    const float4* skr = (const float4*)(sketch + (size_t)m * DDIM);
    float acc = 0.f;
#pragma unroll
    for (int i = 0; i < DDIM / 4; i++) {
        float4 a = qs[i];
        float4 s = skr[i];
        acc += a.x * s.x + a.y * s.y + a.z * s.z + a.w * s.w;
    }
    // block max of |acc|
    float am = fabsf(acc);
#pragma unroll
    for (int off = 16; off; off >>= 1)
        am = fmaxf(am, __shfl_xor_sync(0xffffffffu, am, off));
    if ((m & 31) == 0) red[m >> 5] = am;
    __syncthreads();
    float rm = red[0];
#pragma unroll
    for (int i = 1; i < 8; i++) rm = fmaxf(rm, red[i]);
    rm = fmaxf(rm, 1e-30f);

    const float s    = rm * (1.0f / QSCALE);
    const float S1   = s * 128.0f;
    const float iS1  = 1.0f / S1;
    const float is   = 1.0f / s;
    float h = rintf(acc * iS1);
    float r = acc - h * S1;
    float l = rintf(r * is);
    g_Ah[(size_t)b * MDIM + m] = (signed char)(int)h;
    g_Al[(size_t)b * MDIM + m] = (signed char)(int)l;
    if (m == 0) g_rowscale[b] = s;
}

// ---------------------------------------------------------------
// K2: IMMA GEMM. CTA 128(M) x 128(N), K=256 in 4 chunks of 64.
// Warp tile 64x32 (warp_m = wid&1, warp_n = wid>>1). accH/accL s32.
// cp.async double buffer; rows padded to 80B (validated conflict-free).
// Epilogue: score = (128*accH + accL) * s_row * EST * norm; writes raw
// scores + per-(row, ctile) (max, sumexp) partials.
// ---------------------------------------------------------------
#define ROWB 80                      // 64 data bytes + 16 pad
#define ASZ  (128 * ROWB)            // 10240 B per operand per stage
#define STAGE (3 * ASZ)              // Ah | Al | B = 30720 B
#define SMEM_DYN (2 * STAGE)         // 61440 B

__global__ void __launch_bounds__(256, 1)
gemm_kernel(const float* __restrict__ norms, float* __restrict__ out) {
    extern __shared__ char dsm[];
    __shared__ float  sNorm[NTILE];
    __shared__ float  sRow[128];
    __shared__ float2 sRed[4][128];

    const int tid  = threadIdx.x;
    const int wid  = tid >> 5;
    const int lane = tid & 31;
    const int warp_m = wid & 1;   // 2 over 128 rows (64 each)
    const int warp_n = wid >> 1;  // 4 over 128 cols (32 each)
    const int g = lane >> 2;
    const int q = lane & 3;
    const int row0 = blockIdx.x * 128;
    const int n0   = blockIdx.y * NTILE;

    const uint32_t base = smem_u32(dsm);

    if (tid < NTILE) sNorm[tid] = __ldg(norms + n0 + tid) * EST_CONST;
    else if (tid < NTILE + 128) sRow[tid - NTILE] = g_rowscale[row0 + tid - NTILE];

    int accH[4][4][4], accL[4][4][4];
#pragma unroll
    for (int mt = 0; mt < 4; mt++)
#pragma unroll
        for (int nt = 0; nt < 4; nt++)
#pragma unroll
            for (int c = 0; c < 4; c++) { accH[mt][nt][c] = 0; accL[mt][nt][c] = 0; }

    // per-lane ldmatrix address components (same validated pattern as R4)
    const int aRow = warp_m * 64 + (lane & 7) + ((lane >> 3) & 1) * 8;  // + mt*16
    const int aKh  = (lane >> 4) * 16;
    const int bRow = warp_n * 32 + (lane & 7) + ((lane >> 4) & 1) * 8;  // + ntp*16
    const int bKh  = ((lane >> 3) & 1) * 16;

    auto load_chunk = [&](int kc, int buf) {
        const uint32_t sb = base + buf * STAGE;
        const signed char* srcH = g_Ah + (size_t)row0 * MDIM + kc * 64;
        const signed char* srcL = g_Al + (size_t)row0 * MDIM + kc * 64;
        const signed char* srcB = g_Kq + (size_t)n0 * MDIM + kc * 64;
#pragma unroll
        for (int i = 0; i < 2; i++) {            // 128 rows x 4 segs of 16B
            int idx = tid + i * 256;
            int r = idx >> 2, sg = idx & 3;
            uint32_t so = (uint32_t)(r * ROWB + sg * 16);
            cpa16(sb + so,           srcH + (size_t)r * MDIM + sg * 16);
            cpa16(sb + ASZ + so,     srcL + (size_t)r * MDIM + sg * 16);
            cpa16(sb + 2 * ASZ + so, srcB + (size_t)r * MDIM + sg * 16);
        }
        CP_COMMIT();
    };

    auto compute = [&](int buf) {
        const uint32_t aH = base + buf * STAGE;
        const uint32_t aL = aH + ASZ;
        const uint32_t bB = aH + 2 * ASZ;
#pragma unroll
        for (int kk = 0; kk < 2; kk++) {
            const int kb = kk * 32;  // 32 int8 per k-step
            unsigned ah[4][4], al[4][4], bt[2][4];
#pragma unroll
            for (int mt = 0; mt < 4; mt++) {
                uint32_t ao = (uint32_t)((aRow + mt * 16) * ROWB + kb + aKh);
                ldm_x4(ah[mt], aH + ao);
                ldm_x4(al[mt], aL + ao);
            }
#pragma unroll
            for (int ntp = 0; ntp < 2; ntp++)
                ldm_x4(bt[ntp], bB + (uint32_t)((bRow + ntp * 16) * ROWB + kb + bKh));
#pragma unroll
            for (int mt = 0; mt < 4; mt++)
#pragma unroll
                for (int nt = 0; nt < 4; nt++) {
                    unsigned b2[2] = { bt[nt >> 1][(nt & 1) * 2],
                                       bt[nt >> 1][(nt & 1) * 2 + 1] };
                    imma16832(accH[mt][nt], ah[mt], b2);
                    imma16832(accL[mt][nt], al[mt], b2);
                }
        }
    };

    // ---- pipeline: 4 chunks of K=64, 2-stage ring ----
    load_chunk(0, 0);
#pragma unroll
    for (int kc = 0; kc < 4; kc++) {
        if (kc < 3) {
            load_chunk(kc + 1, (kc + 1) & 1);
            cp_wait<1>();
        } else {
            cp_wait<0>();
        }
        __syncthreads();
        compute(kc & 1);
        __syncthreads();
    }

    // ---- epilogue ----
#pragma unroll
    for (int mt = 0; mt < 4; mt++) {
#pragma unroll
        for (int h = 0; h < 2; h++) {
            const int rloc = warp_m * 64 + mt * 16 + g + h * 8;
            const float srow = sRow[rloc];
            size_t orow = (size_t)(row0 + rloc) * NKEYS + n0;
            float v[8];
            float mymax = -3.0e38f;
#pragma unroll
            for (int nt = 0; nt < 4; nt++) {
                int cl = warp_n * 32 + nt * 8 + 2 * q;
                int t0 = accH[mt][nt][h * 2 + 0] * 128 + accL[mt][nt][h * 2 + 0];
                int t1 = accH[mt][nt][h * 2 + 1] * 128 + accL[mt][nt][h * 2 + 1];
                float v0 = (float)t0 * (sNorm[cl] * srow);
                float v1 = (float)t1 * (sNorm[cl + 1] * srow);
                v[nt * 2] = v0; v[nt * 2 + 1] = v1;
                *reinterpret_cast<float2*>(out + orow + cl) = make_float2(v0, v1);
                mymax = fmaxf(mymax, fmaxf(v0, v1));
            }
            float s = 0.f;
#pragma unroll
            for (int i = 0; i < 8; i++) s += __expf(v[i] - mymax);
#pragma unroll
            for (int off = 1; off <= 2; off <<= 1) {
                float mo = __shfl_xor_sync(0xffffffffu, mymax, off);
                float so = __shfl_xor_sync(0xffffffffu, s, off);
                float nm = fmaxf(mymax, mo);
                s = s * __expf(mymax - nm) + so * __expf(mo - nm);
                mymax = nm;
            }
            if (q == 0) sRed[warp_n][rloc] = make_float2(mymax, s);
        }
    }
    __syncthreads();
    if (tid < 128) {
        float2 a = sRed[0][tid], b = sRed[1][tid];
        float2 c = sRed[2][tid], d = sRed[3][tid];
        float M = fmaxf(fmaxf(a.x, b.x), fmaxf(c.x, d.x));
        float S = a.y * __expf(a.x - M) + b.y * __expf(b.x - M) +
                  c.y * __expf(c.x - M) + d.y * __expf(d.x - M);
        size_t p = ((size_t)(row0 + tid) * CTILES + blockIdx.y) * 2;
        g_part[p]     = M;
        g_part[p + 1] = S;
    }
}

// ---------------------------------------------------------------
// K3: per-row log-sum-exp reduction of 256 partials
// ---------------------------------------------------------------
__global__ void reduce_kernel() {
    int b = blockIdx.x, t = threadIdx.x;
    size_t base = ((size_t)b * CTILES + t) * 2;
    float m = g_part[base];
    float s = g_part[base + 1];
#pragma unroll
    for (int off = 16; off; off >>= 1) {
        float mo = __shfl_xor_sync(0xffffffffu, m, off);
        float so = __shfl_xor_sync(0xffffffffu, s, off);
        float nm = fmaxf(m, mo);
        s = s * __expf(m - nm) + so * __expf(mo - nm);
        m = nm;
    }
    __shared__ float sm[8], ss[8];
    if ((t & 31) == 0) { sm[t >> 5] = m; ss[t >> 5] = s; }
    __syncthreads();
    if (t < 32) {
        if (t < 8) { m = sm[t]; s = ss[t]; }
        else       { m = -3.0e38f; s = 0.f; }
#pragma unroll
        for (int off = 4; off; off >>= 1) {
            float mo = __shfl_xor_sync(0xffffffffu, m, off);
            float so = __shfl_xor_sync(0xffffffffu, s, off);
            float nm = fmaxf(m, mo);
            s = s * __expf(m - nm) + so * __expf(mo - nm);
            m = nm;
        }
        if (t == 0) g_rowstats[b] = make_float2(m, 1.0f / s);
    }
}

// ---------------------------------------------------------------
// K4: out = exp(score - M) * invS   (in-place over d_out)
// ---------------------------------------------------------------
__global__ void norm_kernel(float* __restrict__ out) {
    const size_t total4 = (size_t)BATCH * NKEYS / 4;
    size_t stride = (size_t)gridDim.x * blockDim.x;
    for (size_t i4 = (size_t)blockIdx.x * blockDim.x + threadIdx.x;
         i4 < total4; i4 += stride) {
        int b = (int)(i4 >> 13);  // 8192 float4 per row
        float2 st = __ldg(&g_rowstats[b]);
        float4 v = reinterpret_cast<float4*>(out)[i4];
        v.x = __expf(v.x - st.x) * st.y;
        v.y = __expf(v.y - st.x) * st.y;
        v.z = __expf(v.z - st.x) * st.y;
        v.w = __expf(v.w - st.x) * st.y;
        reinterpret_cast<float4*>(out)[i4] = v;
    }
}

// ---------------------------------------------------------------
extern "C" void kernel_launch(void* const* d_in, const int* in_sizes, int n_in,
                              void* d_out, int out_size) {
    const float* query  = (const float*)d_in[0];  // [2048, 128]
    const float* keys   = (const float*)d_in[1];  // [32768, 256] (+/-1)
    const float* norms  = (const float*)d_in[2];  // [32768]
    const float* sketch = (const float*)d_in[3];  // [256, 128]
    float* out = (float*)d_out;                   // [2048, 32768]

    cudaFuncSetAttribute(gemm_kernel, cudaFuncAttributeMaxDynamicSharedMemorySize, SMEM_DYN);

    convert_keys<<<(NKEYS * MDIM / 4) / 256, 256>>>(keys);
    project_kernel<<<BATCH, 256>>>(query, sketch);
    dim3 g2(BATCH / 128, CTILES);  // m-fastest: slabs share key tiles in-wave
    gemm_kernel<<<g2, 256, SMEM_DYN>>>(norms, out);
    reduce_kernel<<<BATCH, 256>>>();
    norm_kernel<<<16384, 256>>>(out);
}

// round 7
// speedup vs baseline: 1.6350x; 1.6350x over previous
#include <cuda_runtime.h>
#include <cuda_bf16.h>
#include <cstdint>

#define BATCH 2048
#define DDIM  128
#define MDIM  256
#define NKEYS 32768
#define NTILE 128                   // keys per gemm CTA tile
#define CTILES (NKEYS / NTILE)      // 256
#define SLABROWS 128
#define NSLABS (BATCH / SLABROWS)   // 16
#define NORM_PER_SLAB 16
#define ROWS_PER_NORM (SLABROWS / NORM_PER_SLAB)   // 8
#define GROUP (CTILES + NORM_PER_SLAB)             // 272 CTAs per slab group
#define EST_CONST 0.0048957583f     // float32(sqrt(pi/2)/256)

// -------- static device scratch (no allocations allowed) --------
__device__ __align__(16) __nv_bfloat16 g_Ahi[BATCH * MDIM];
__device__ __align__(16) __nv_bfloat16 g_Alo[BATCH * MDIM];
__device__ __align__(16) __nv_bfloat16 g_Kbf[(size_t)NKEYS * MDIM];
__device__ float  g_part[(size_t)BATCH * CTILES * 2];   // (max,sum) per row,ctile
__device__ float2 g_rowstats[BATCH];
__device__ int    g_slabCnt[NSLABS];
__device__ int    g_slabReady[NSLABS];

// ---------------- PTX helpers (compute_103-safe) ----------------
__device__ __forceinline__ uint32_t smem_u32(const void* p) {
    uint32_t a;
    asm("{ .reg .u64 t; cvta.to.shared.u64 t, %1; cvt.u32.u64 %0, t; }" : "=r"(a) : "l"(p));
    return a;
}
__device__ __forceinline__ void cpa16(uint32_t dst, const void* src) {
    asm volatile("cp.async.cg.shared.global [%0], [%1], 16;" :: "r"(dst), "l"(src));
}
#define CP_COMMIT() asm volatile("cp.async.commit_group;" ::: "memory")
template <int N> __device__ __forceinline__ void cp_wait() {
    asm volatile("cp.async.wait_group %0;" :: "n"(N) : "memory");
}
__device__ __forceinline__ void ldm_x4(unsigned* r, uint32_t addr) {
    asm volatile("ldmatrix.sync.aligned.m8n8.x4.shared.b16 {%0,%1,%2,%3}, [%4];"
                 : "=r"(r[0]), "=r"(r[1]), "=r"(r[2]), "=r"(r[3]) : "r"(addr));
}
__device__ __forceinline__ void mma16816(float* c, const unsigned* a, const unsigned* b) {
    asm volatile(
        "mma.sync.aligned.m16n8k16.row.col.f32.bf16.bf16.f32 "
        "{%0,%1,%2,%3}, {%4,%5,%6,%7}, {%8,%9}, {%0,%1,%2,%3};\n"
        : "+f"(c[0]), "+f"(c[1]), "+f"(c[2]), "+f"(c[3])
        : "r"(a[0]), "r"(a[1]), "r"(a[2]), "r"(a[3]), "r"(b[0]), "r"(b[1]));
}

// ---------------------------------------------------------------
// K0: zero the per-launch handshake state
// ---------------------------------------------------------------
__global__ void init_kernel() {
    if (threadIdx.x < NSLABS) {
        g_slabCnt[threadIdx.x] = 0;
        g_slabReady[threadIdx.x] = 0;
    }
}

// ---------------------------------------------------------------
// K1: fused  (a) keys fp32(+/-1) -> bf16 (exact)   [bids 0..8191]
//            (b) PQ = query @ sketch^T, bf16 hi/lo [bids 8192..10239]
// ---------------------------------------------------------------
__global__ void prologue_kernel(const float* __restrict__ keys,
                                const float* __restrict__ query,
                                const float* __restrict__ sketch) {
    if (blockIdx.x < 8192) {   // -------- convert keys --------
        size_t i = (size_t)blockIdx.x * 256 + threadIdx.x;  // one float4 each
        float4 v = __ldg((const float4*)keys + i);
        __nv_bfloat162 a = __floats2bfloat162_rn(v.x, v.y);
        __nv_bfloat162 b = __floats2bfloat162_rn(v.z, v.w);
        ((__nv_bfloat162*)g_Kbf)[2 * i]     = a;
        ((__nv_bfloat162*)g_Kbf)[2 * i + 1] = b;
        return;
    }
    // -------- project one batch row --------
    __shared__ float4 qs[DDIM / 4];
    const int b = blockIdx.x - 8192;
    const int m = threadIdx.x;  // 0..255
    if (m < DDIM / 4)
        qs[m] = ((const float4*)(query + (size_t)b * DDIM))[m];
    __syncthreads();

    const float4* skr = (const float4*)(sketch + (size_t)m * DDIM);
    float acc = 0.f;
#pragma unroll
    for (int i = 0; i < DDIM / 4; i++) {
        float4 a = qs[i];
        float4 s = skr[i];
        acc += a.x * s.x + a.y * s.y + a.z * s.z + a.w * s.w;
    }
    __nv_bfloat16 hi = __float2bfloat16(acc);
    float rem = acc - __bfloat162float(hi);
    g_Ahi[(size_t)b * MDIM + m] = hi;
    g_Alo[(size_t)b * MDIM + m] = __float2bfloat16(rem);
}

// ---------------------------------------------------------------
// K2: fused GEMM + softmax.
// 1D grid of 16 slab-groups: [256 gemm CTAs][16 norm CTAs] each.
// gemm CTA: 128(M) x 128(N), K=256 in 8 chunks of 32, hi/lo folded,
//   cp.async double buffer, occupancy 2. Writes raw scaled scores +
//   per-(row,ctile) (max,sumexp). Last CTA of slab reduces rowstats
//   and raises g_slabReady[slab].
// norm CTA: spins on g_slabReady, then normalizes 8 rows in place
//   (reads hit L2 - slab written 1-2 waves earlier).
// ---------------------------------------------------------------
#define ROWB 80                      // 64 data bytes + 16 pad (conflict-free)
#define ASZ  (128 * ROWB)            // 10240 B per operand per stage
#define STAGE (3 * ASZ)              // Ahi | Alo | B = 30720 B
#define SMEM_DYN (2 * STAGE)         // 61440 B

__global__ void __launch_bounds__(256, 2)
fused_kernel(const float* __restrict__ norms, float* __restrict__ out) {
    const int slab = blockIdx.x / GROUP;
    const int w    = blockIdx.x % GROUP;
    const int tid  = threadIdx.x;

    // ================= NORM CTA =================
    if (w >= CTILES) {
        const int part = w - CTILES;
        if (tid == 0) {
            while (atomicAdd(&g_slabReady[slab], 0) == 0) __nanosleep(128);
        }
        __syncthreads();
        __threadfence();
#pragma unroll
        for (int rr = 0; rr < ROWS_PER_NORM; rr++) {
            const int row = slab * SLABROWS + part * ROWS_PER_NORM + rr;
            const float2 st = g_rowstats[row];
            float4* p = (float4*)(out + (size_t)row * NKEYS);
            for (int i = tid; i < NKEYS / 4; i += 256) {
                float4 v = p[i];
                v.x = __expf(v.x - st.x) * st.y;
                v.y = __expf(v.y - st.x) * st.y;
                v.z = __expf(v.z - st.x) * st.y;
                v.w = __expf(v.w - st.x) * st.y;
                p[i] = v;
            }
        }
        return;
    }

    // ================= GEMM CTA =================
    extern __shared__ char dsm[];
    __shared__ float  sNorm[NTILE];
    __shared__ float2 sRed[4][128];
    __shared__ int    sLast;

    const int ctile = w;
    const int row0  = slab * SLABROWS;
    const int n0    = ctile * NTILE;
    const int wid   = tid >> 5;
    const int lane  = tid & 31;
    const int warp_m = wid & 1;   // 2 over 128 rows (64 each)
    const int warp_n = wid >> 1;  // 4 over 128 cols (32 each)
    const int g = lane >> 2;
    const int q = lane & 3;

    const uint32_t base = smem_u32(dsm);

    if (tid < NTILE) sNorm[tid] = __ldg(norms + n0 + tid) * EST_CONST;

    float acc[4][4][4];
#pragma unroll
    for (int mt = 0; mt < 4; mt++)
#pragma unroll
        for (int nt = 0; nt < 4; nt++)
#pragma unroll
            for (int c = 0; c < 4; c++) acc[mt][nt][c] = 0.f;

    // per-lane ldmatrix address components (validated R4/R5 pattern)
    const int aRow = warp_m * 64 + (lane & 7) + ((lane >> 3) & 1) * 8;  // + mt*16
    const int aKh  = (lane >> 4) * 16;
    const int bRow = warp_n * 32 + (lane & 7) + ((lane >> 4) & 1) * 8;  // + ntp*16
    const int bKh  = ((lane >> 3) & 1) * 16;

    auto load_chunk = [&](int kc, int buf) {
        const uint32_t sb = base + buf * STAGE;
        const __nv_bfloat16* srcH = g_Ahi + (size_t)row0 * MDIM + kc * 32;
        const __nv_bfloat16* srcL = g_Alo + (size_t)row0 * MDIM + kc * 32;
        const __nv_bfloat16* srcB = g_Kbf + (size_t)n0 * MDIM + kc * 32;
#pragma unroll
        for (int i = 0; i < 2; i++) {            // 128 rows x 4 segs of 16B
            int idx = tid + i * 256;
            int r = idx >> 2, sg = idx & 3;
            uint32_t so = (uint32_t)(r * ROWB + sg * 16);
            cpa16(sb + so,           srcH + (size_t)r * MDIM + sg * 8);
            cpa16(sb + ASZ + so,     srcL + (size_t)r * MDIM + sg * 8);
            cpa16(sb + 2 * ASZ + so, srcB + (size_t)r * MDIM + sg * 8);
        }
        CP_COMMIT();
    };

    auto compute = [&](int buf) {
        const uint32_t aH = base + buf * STAGE;
        const uint32_t aL = aH + ASZ;
        const uint32_t bB = aH + 2 * ASZ;
#pragma unroll
        for (int kk = 0; kk < 2; kk++) {
            const int kb = kk * 32;  // 16 bf16 = 32 bytes per k-step
            unsigned ah[4][4], al[4][4], bt[2][4];
#pragma unroll
            for (int mt = 0; mt < 4; mt++) {
                uint32_t ao = (uint32_t)((aRow + mt * 16) * ROWB + kb + aKh);
                ldm_x4(ah[mt], aH + ao);
                ldm_x4(al[mt], aL + ao);
            }
#pragma unroll
            for (int ntp = 0; ntp < 2; ntp++)
                ldm_x4(bt[ntp], bB + (uint32_t)((bRow + ntp * 16) * ROWB + kb + bKh));
#pragma unroll
            for (int mt = 0; mt < 4; mt++)
#pragma unroll
                for (int nt = 0; nt < 4; nt++) {
                    unsigned b2[2] = { bt[nt >> 1][(nt & 1) * 2],
                                       bt[nt >> 1][(nt & 1) * 2 + 1] };
                    mma16816(acc[mt][nt], ah[mt], b2);
                    mma16816(acc[mt][nt], al[mt], b2);
                }
        }
    };

    // ---- pipeline: 8 chunks of K=32, 2-stage ring ----
    load_chunk(0, 0);
#pragma unroll
    for (int kc = 0; kc < 8; kc++) {
        if (kc < 7) {
            load_chunk(kc + 1, (kc + 1) & 1);
            cp_wait<1>();
        } else {
            cp_wait<0>();
        }
        __syncthreads();
        compute(kc & 1);
        __syncthreads();
    }

    // ---- epilogue: scale, write raw scores, (max,sumexp) partials ----
#pragma unroll
    for (int mt = 0; mt < 4; mt++) {
#pragma unroll
        for (int h = 0; h < 2; h++) {
            const int rloc = warp_m * 64 + mt * 16 + g + h * 8;
            size_t orow = (size_t)(row0 + rloc) * NKEYS + n0;
            float v[8];
            float mymax = -3.0e38f;
#pragma unroll
            for (int nt = 0; nt < 4; nt++) {
                int cl = warp_n * 32 + nt * 8 + 2 * q;
                float v0 = acc[mt][nt][h * 2 + 0] * sNorm[cl];
                float v1 = acc[mt][nt][h * 2 + 1] * sNorm[cl + 1];
                v[nt * 2] = v0; v[nt * 2 + 1] = v1;
                *reinterpret_cast<float2*>(out + orow + cl) = make_float2(v0, v1);
                mymax = fmaxf(mymax, fmaxf(v0, v1));
            }
            float s = 0.f;
#pragma unroll
            for (int i = 0; i < 8; i++) s += __expf(v[i] - mymax);
#pragma unroll
            for (int off = 1; off <= 2; off <<= 1) {
                float mo = __shfl_xor_sync(0xffffffffu, mymax, off);
                float so = __shfl_xor_sync(0xffffffffu, s, off);
                float nm = fmaxf(mymax, mo);
                s = s * __expf(mymax - nm) + so * __expf(mo - nm);
                mymax = nm;
            }
            if (q == 0) sRed[warp_n][rloc] = make_float2(mymax, s);
        }
    }
    __syncthreads();
    if (tid < 128) {
        float2 a = sRed[0][tid], b = sRed[1][tid];
        float2 c = sRed[2][tid], d = sRed[3][tid];
        float M = fmaxf(fmaxf(a.x, b.x), fmaxf(c.x, d.x));
        float S = a.y * __expf(a.x - M) + b.y * __expf(b.x - M) +
                  c.y * __expf(c.x - M) + d.y * __expf(d.x - M);
        size_t p = ((size_t)(row0 + tid) * CTILES + ctile) * 2;
        g_part[p]     = M;
        g_part[p + 1] = S;
    }

    // ---- slab completion handshake ----
    __threadfence();
    __syncthreads();
    if (tid == 0) {
        int old = atomicAdd(&g_slabCnt[slab], 1);
        sLast = (old == CTILES - 1);
    }
    __syncthreads();
    if (sLast) {
        __threadfence();
        if (tid < SLABROWS) {
            const int row = row0 + tid;
            const float2* pp = (const float2*)(g_part + (size_t)row * CTILES * 2);
            float m = -3.0e38f, s = 0.f;
            for (int ct = 0; ct < CTILES; ct++) {
                float2 x = pp[ct];
                float nm = fmaxf(m, x.x);
                s = s * __expf(m - nm) + x.y * __expf(x.x - nm);
                m = nm;
            }
            g_rowstats[row] = make_float2(m, 1.0f / s);
        }
        __syncthreads();
        __threadfence();
        if (tid == 0) atomicExch(&g_slabReady[slab], 1);
    }
}

// ---------------------------------------------------------------
extern "C" void kernel_launch(void* const* d_in, const int* in_sizes, int n_in,
                              void* d_out, int out_size) {
    const float* query  = (const float*)d_in[0];  // [2048, 128]
    const float* keys   = (const float*)d_in[1];  // [32768, 256] (+/-1)
    const float* norms  = (const float*)d_in[2];  // [32768]
    const float* sketch = (const float*)d_in[3];  // [256, 128]
    float* out = (float*)d_out;                   // [2048, 32768]

    cudaFuncSetAttribute(fused_kernel, cudaFuncAttributeMaxDynamicSharedMemorySize, SMEM_DYN);

    init_kernel<<<1, 32>>>();
    prologue_kernel<<<8192 + BATCH, 256>>>(keys, query, sketch);
    fused_kernel<<<NSLABS * GROUP, 256, SMEM_DYN>>>(norms, out);
}